// round 1
// baseline (speedup 1.0000x reference)
#include <cuda_runtime.h>

// SLAYER SNN: s2 = spike(psp(dense(W2, spike(psp(dense(W1, x))))))
// (psp and dense commuted: both linear, so dense first -> FIR on fewer channels)

#define BB    32
#define NIN   2312
#define NHID  512
#define NOUT  10
#define TT    350
#define TK    100
#define WPT   73          // ceil(NIN/32)

#define THETA  10.0f
#define D_REF  0.36787944117144233f    // exp(-1)
#define C_REF  -54.365636569180905f    // -2*10*e

// -------- scratch (device globals; no cudaMalloc allowed) --------
__device__ float    g_W1T[NIN * NHID];          // 4.7 MB  W1 transposed [i][h]
__device__ unsigned g_PK [BB * TT * WPT];       // 3.3 MB  packed spike bits [b][t][w]
__device__ float    g_Y1 [BB * TT * NHID];      // 22.9 MB dense(W1,x), t-major [b][t][h]
__device__ float    g_U1 [BB * TT * NHID];      // 22.9 MB psp(Y1)
__device__ float    g_S1 [BB * TT * NHID];      // 22.9 MB hidden spikes
__device__ float    g_Y2 [BB * TT * NOUT];
__device__ float    g_U2 [BB * TT * NOUT];

// -------- W1 [h][i] -> W1T [i][h] --------
__global__ void k_transposeW1(const float* __restrict__ W1) {
    __shared__ float s[32][33];
    int i = blockIdx.x * 32 + threadIdx.x;
    int h = blockIdx.y * 32 + threadIdx.y;
    if (i < NIN && h < NHID) s[threadIdx.y][threadIdx.x] = W1[h * NIN + i];
    __syncthreads();
    int i2 = blockIdx.x * 32 + threadIdx.y;
    int h2 = blockIdx.y * 32 + threadIdx.x;
    if (i2 < NIN && h2 < NHID) g_W1T[i2 * NHID + h2] = s[threadIdx.x][threadIdx.y];
}

// -------- pack input spikes into bitmask, [b][i][t] -> bits[b][t][i/32] --------
__global__ void k_pack(const float* __restrict__ A) {
    __shared__ unsigned char s[32][33];
    int b  = blockIdx.x;
    int i0 = blockIdx.y * 32;
    int t0 = blockIdx.z * 32;
    int i = i0 + threadIdx.y;
    int t = t0 + threadIdx.x;
    unsigned char bit = 0;
    if (i < NIN && t < TT) bit = (A[(b * NIN + i) * TT + t] > 0.5f) ? 1 : 0;
    s[threadIdx.y][threadIdx.x] = bit;
    __syncthreads();
    if (threadIdx.y == 0) {
        int t2 = t0 + threadIdx.x;
        if (t2 < TT) {
            unsigned w = 0;
#pragma unroll
            for (int y = 0; y < 32; y++) w |= ((unsigned)s[y][threadIdx.x]) << y;
            g_PK[(b * TT + t2) * WPT + blockIdx.y] = w;
        }
    }
}

// -------- sparse SpMM: Y1[b][t][h] = sum over active inputs i of W1T[i][h] --------
// one block per (b,t) column; deterministic (ascending-i) accumulation order
__global__ void k_spmm1() {
    __shared__ unsigned short sidx[NIN];
    __shared__ int soff[WPT];
    __shared__ int stotal;
    int bt  = blockIdx.x;
    int tid = threadIdx.x;

    unsigned w = 0;
    if (tid < WPT) {
        w = g_PK[bt * WPT + tid];
        soff[tid] = __popc(w);
    }
    __syncthreads();
    if (tid == 0) {
        int run = 0;
        for (int j = 0; j < WPT; j++) { int c = soff[j]; soff[j] = run; run += c; }
        stotal = run;
    }
    __syncthreads();
    if (tid < WPT) {
        int off = tid == 0 ? 0 : soff[tid];
        unsigned ww = w;
        while (ww) {
            int bpos = __ffs(ww) - 1;
            ww &= ww - 1;
            sidx[off++] = (unsigned short)(tid * 32 + bpos);
        }
    }
    __syncthreads();

    int n = stotal;
    float a0 = 0.f, a1 = 0.f, a2 = 0.f, a3 = 0.f;
    int j = 0;
    for (; j + 4 <= n; j += 4) {
        int i0 = sidx[j], i1 = sidx[j + 1], i2 = sidx[j + 2], i3 = sidx[j + 3];
        a0 += g_W1T[i0 * NHID + tid];
        a1 += g_W1T[i1 * NHID + tid];
        a2 += g_W1T[i2 * NHID + tid];
        a3 += g_W1T[i3 * NHID + tid];
    }
    float acc = (a0 + a1) + (a2 + a3);
    for (; j < n; j++) acc += g_W1T[(int)sidx[j] * NHID + tid];
    g_Y1[bt * NHID + tid] = acc;
}

// -------- FIR psp filter, layer 1: U1 = eps (*) Y1 along t --------
// block = (b, 32-wide h chunk); tile [T][32] in shared, warp rg handles t = rg, rg+8, ...
__global__ void k_fir1() {
    __shared__ float tile[TT * 32];
    __shared__ float eps[TK];
    int b  = blockIdx.x / (NHID / 32);
    int h0 = (blockIdx.x % (NHID / 32)) * 32;
    int tid = threadIdx.x;

    if (tid < TK) eps[tid] = (float)((tid / 10.0) * exp(1.0 - tid / 10.0));
    for (int idx = tid; idx < TT * 32; idx += 256) {
        int t = idx >> 5, hl = idx & 31;
        tile[idx] = g_Y1[(b * TT + t) * NHID + h0 + hl];
    }
    __syncthreads();

    int hl = tid & 31, rg = tid >> 5;     // 8 warps x 32 lanes
    for (int t = rg; t < TT; t += 8) {
        float acc = 0.f;
        int kmax = min(t, TK - 1);
#pragma unroll 4
        for (int k = 1; k <= kmax; k++)    // eps[0] == 0 exactly
            acc += eps[k] * tile[(t - k) * 32 + hl];
        g_U1[(b * TT + t) * NHID + h0 + hl] = acc;
    }
}

// -------- spike layer 1: threshold + alpha refractory (2-state IIR), seq in t --------
__global__ void k_spike1() {
    int b = blockIdx.x, h = threadIdx.x;
    float a = 0.f, rb = 0.f;
    const float* up = g_U1 + (size_t)b * TT * NHID + h;
    float*       sp = g_S1 + (size_t)b * TT * NHID + h;
    for (int t = 0; t < TT; t++) {
        float u = up[t * NHID] + C_REF * rb;
        float s = (u >= THETA) ? 1.f : 0.f;
        float an = D_REF * a + s;
        rb = D_REF * rb + D_REF * a;
        a = an;
        sp[t * NHID] = s;
    }
}

// -------- small GEMM: Y2[b][t][o] = W2[o][:] . S1[b][t][:] --------
__global__ void k_mm2(const float* __restrict__ W2) {
    __shared__ float sh[NHID];
    int bt = blockIdx.x;
    int tid = threadIdx.x;
    sh[tid] = g_S1[bt * NHID + tid];
    __syncthreads();
    int w = tid >> 5, lane = tid & 31;
    if (w < NOUT) {
        float acc = 0.f;
#pragma unroll 4
        for (int h = lane; h < NHID; h += 32) acc += W2[w * NHID + h] * sh[h];
#pragma unroll
        for (int off = 16; off; off >>= 1) acc += __shfl_down_sync(0xffffffffu, acc, off);
        if (lane == 0) g_Y2[bt * NOUT + w] = acc;
    }
}

// -------- FIR psp filter, layer 2 --------
__global__ void k_fir2() {
    __shared__ float y[TT * NOUT];     // 14 KB
    __shared__ float eps[TK];
    int b = blockIdx.x, tid = threadIdx.x;
    if (tid < TK) eps[tid] = (float)((tid / 10.0) * exp(1.0 - tid / 10.0));
    for (int i = tid; i < TT * NOUT; i += 256) y[i] = g_Y2[b * TT * NOUT + i];
    __syncthreads();
    for (int i = tid; i < TT * NOUT; i += 256) {
        int t = i / NOUT, o = i - t * NOUT;
        float acc = 0.f;
        int kmax = min(t, TK - 1);
#pragma unroll 4
        for (int k = 1; k <= kmax; k++) acc += eps[k] * y[(t - k) * NOUT + o];
        g_U2[b * TT * NOUT + i] = acc;
    }
}

// -------- spike layer 2 -> final output [B][NOUT][T] --------
__global__ void k_spike2(float* __restrict__ out) {
    int tid = threadIdx.x;          // 320 = B*NOUT
    int b = tid / NOUT, o = tid - b * NOUT;
    float a = 0.f, rb = 0.f;
    for (int t = 0; t < TT; t++) {
        float u = g_U2[(b * TT + t) * NOUT + o] + C_REF * rb;
        float s = (u >= THETA) ? 1.f : 0.f;
        float an = D_REF * a + s;
        rb = D_REF * rb + D_REF * a;
        a = an;
        out[(b * NOUT + o) * TT + t] = s;
    }
}

extern "C" void kernel_launch(void* const* d_in, const int* in_sizes, int n_in,
                              void* d_out, int out_size) {
    const float* A  = nullptr;   // spikeInput [B][NIN][T]
    const float* W1 = nullptr;   // [NHID][NIN]
    const float* W2 = nullptr;   // [NOUT][NHID]
    for (int i = 0; i < n_in; i++) {
        if      (in_sizes[i] == BB * NIN * TT) A  = (const float*)d_in[i];
        else if (in_sizes[i] == NHID * NIN)    W1 = (const float*)d_in[i];
        else if (in_sizes[i] == NOUT * NHID)   W2 = (const float*)d_in[i];
    }
    float* out = (float*)d_out;

    k_transposeW1<<<dim3((NIN + 31) / 32, NHID / 32), dim3(32, 32)>>>(W1);
    k_pack<<<dim3(BB, WPT, (TT + 31) / 32), dim3(32, 32)>>>(A);
    k_spmm1<<<BB * TT, NHID>>>();
    k_fir1<<<BB * (NHID / 32), 256>>>();
    k_spike1<<<BB, NHID>>>();
    k_mm2<<<BB * TT, NHID>>>(W2);
    k_fir2<<<BB, 256>>>();
    k_spike2<<<1, BB * NOUT>>>(out);
}

// round 2
// speedup vs baseline: 1.0613x; 1.0613x over previous
#include <cuda_runtime.h>
#include <math.h>

#define BB    32
#define NIN   2312
#define NHID  512
#define NOUT  10
#define TT    350
#define WPT   73              // ceil(NIN/32)
#define IDXCAP 320            // max active inputs per (b,t) column (mean 115.6, 13 sigma margin)
#define NROW  2313            // 2312 real rows + 1 zero pad row

#define THETA  10.0f
#define D_REF  0.36787944117144233f    // exp(-1)
#define C_REF  -54.365636569180905f    // -2*10*e

// ---------------- scratch (device globals; no cudaMalloc allowed) ----------------
__device__ float          g_W1Tc[32 * NROW * 16];     // chunked W1^T: [hc][i][16]   4.74 MB
__device__ unsigned       g_PK  [BB * TT * WPT];      // packed spike bits           3.3 MB
__device__ unsigned short g_IDX [BB * TT * IDXCAP];   // per-column active indices   7.2 MB
__device__ int            g_CNT [BB * TT];            // padded counts (multiple of 8)
__device__ float          g_Y1  [BB * TT * NHID];     // dense(W1,x), t-major        22.9 MB
__device__ float          g_S1  [BB * TT * NHID];     // hidden spikes, t-major      22.9 MB

// ---------------- W1 [h][i] -> chunked W1T [h/16][i][h%16], pad row i=2312 = 0 ----
__global__ void k_prep(const float* __restrict__ W1) {
    __shared__ float s[32][33];
    int i = blockIdx.x * 32 + threadIdx.x;
    int h = blockIdx.y * 32 + threadIdx.y;
    s[threadIdx.y][threadIdx.x] = (i < NIN && h < NHID) ? W1[h * NIN + i] : 0.f;
    __syncthreads();
    int i2 = blockIdx.x * 32 + threadIdx.y;
    int h2 = blockIdx.y * 32 + threadIdx.x;
    if (i2 < NROW) {
        int hc = h2 >> 4, hl = h2 & 15;
        g_W1Tc[((size_t)hc * NROW + i2) * 16 + hl] = s[threadIdx.x][threadIdx.y];
    }
}

// ---------------- pack input spikes: [b][i][t] -> bits [b][t][i/32] ----------------
__global__ void k_pack(const float* __restrict__ A) {
    __shared__ unsigned char s[32][33];
    int b  = blockIdx.x;
    int i0 = blockIdx.y * 32;
    int t0 = blockIdx.z * 32;
    int i = i0 + threadIdx.y;
    int t = t0 + threadIdx.x;
    unsigned char bit = 0;
    if (i < NIN && t < TT) bit = (A[((size_t)b * NIN + i) * TT + t] > 0.5f) ? 1 : 0;
    s[threadIdx.y][threadIdx.x] = bit;
    __syncthreads();
    if (threadIdx.y == 0) {
        int t2 = t0 + threadIdx.x;
        if (t2 < TT) {
            unsigned w = 0;
#pragma unroll
            for (int y = 0; y < 32; y++) w |= ((unsigned)s[y][threadIdx.x]) << y;
            g_PK[(b * TT + t2) * WPT + blockIdx.y] = w;
        }
    }
}

// ---------------- per-(b,t) index list, padded to multiple of 8 with zero-row ----
__global__ void k_extract() {
    __shared__ int cnt[WPT];
    __shared__ int off[WPT + 1];
    __shared__ unsigned wsh[WPT];
    int bt = blockIdx.x, tid = threadIdx.x;
    if (tid < WPT) {
        unsigned w = g_PK[bt * WPT + tid];
        wsh[tid] = w; cnt[tid] = __popc(w);
    }
    __syncthreads();
    if (tid == 0) {
        int r = 0;
        for (int j = 0; j < WPT; j++) { off[j] = r; r += cnt[j]; }
        off[WPT] = r;
        int pad = (r + 7) & ~7; if (pad > IDXCAP) pad = IDXCAP;
        g_CNT[bt] = pad;
    }
    __syncthreads();
    if (tid < WPT) {
        int o = off[tid]; unsigned w = wsh[tid];
        while (w) {
            int bp = __ffs(w) - 1; w &= w - 1;
            if (o < IDXCAP) g_IDX[(size_t)bt * IDXCAP + o] = (unsigned short)(tid * 32 + bp);
            o++;
        }
    }
    int total = off[WPT];
    int pad = (total + 7) & ~7; if (pad > IDXCAP) pad = IDXCAP;
    for (int j = total + tid; j < pad; j += blockDim.x)
        g_IDX[(size_t)bt * IDXCAP + j] = (unsigned short)(NROW - 1);  // zero row
}

// ---------------- SpMM: smem-resident W1T slice, 448 columns per block ----------
#define SPMM_SMEM (NROW * 64 + 64 * IDXCAP * 2 + 256)
__global__ void __launch_bounds__(256, 1) k_spmm() {
    extern __shared__ char smraw[];
    float4*         sW = (float4*)smraw;                                // NROW x 4 float4 (148 KB)
    unsigned short* sI = (unsigned short*)(smraw + NROW * 64);          // 64 x IDXCAP  (40 KB)
    int*            sC = (int*)(smraw + NROW * 64 + 64 * IDXCAP * 2);   // 64
    int tid = threadIdx.x;
    int hc  = blockIdx.y;                 // 32 h-chunks of 16
    int grp = blockIdx.x;                 // 25 groups of 448 columns

    const float4* wsrc = (const float4*)(g_W1Tc + (size_t)hc * NROW * 16);
    for (int i = tid; i < NROW * 4; i += 256) sW[i] = wsrc[i];

    int wid = tid >> 5, lane = tid & 31;
    for (int p = 0; p < 7; p++) {
        int col0 = grp * 448 + p * 64;
        __syncthreads();                                // prev pass done before reuse
        if (tid < 64) sC[tid] = g_CNT[col0 + tid];
        for (int c = wid; c < 64; c += 8) {
            int n = g_CNT[col0 + c];                    // padded, even
            const unsigned* gs = (const unsigned*)(g_IDX + (size_t)(col0 + c) * IDXCAP);
            unsigned* ds = (unsigned*)(sI + c * IDXCAP);
            for (int j = lane; j < (n >> 1); j += 32) ds[j] = gs[j];
        }
        __syncthreads();
        int c = tid >> 2, h4 = tid & 3;                 // 4 threads x float4 = 16 h
        int n = sC[c];
        const unsigned short* il = sI + c * IDXCAP;
        float x0=0,y0=0,z0=0,w0=0, x1=0,y1=0,z1=0,w1=0;
#pragma unroll 4
        for (int j = 0; j < n; j += 2) {
            float4 wa = sW[(int)il[j]     * 4 + h4];
            float4 wb = sW[(int)il[j + 1] * 4 + h4];
            x0 += wa.x; y0 += wa.y; z0 += wa.z; w0 += wa.w;
            x1 += wb.x; y1 += wb.y; z1 += wb.z; w1 += wb.w;
        }
        float4 r; r.x = x0 + x1; r.y = y0 + y1; r.z = z0 + z1; r.w = w0 + w1;
        ((float4*)g_Y1)[(size_t)(col0 + c) * 128 + hc * 4 + h4] = r;
    }
}

// ---------------- FIR1 (register-blocked) fused with spike IIR -------------------
#define FPAD  112
#define TROWS (FPAD + 384)    // 496
#define FIR_SMEM ((TROWS * 32 + TT * 32 + 128) * 4)
__global__ void __launch_bounds__(256, 2) k_fir_spike1() {
    extern __shared__ float sm[];
    float* tile = sm;                     // [TROWS][32], zero-padded front/back
    float* usm  = sm + TROWS * 32;        // [350][32]
    float* epsx = usm + TT * 32;          // epsx[i] = eps(i-7), 0 outside [1,99]
    int tid = threadIdx.x;
    int b   = blockIdx.x >> 4;
    int h0  = (blockIdx.x & 15) * 32;

    if (tid < 128) {
        int j = tid - 7;
        epsx[tid] = (j >= 1 && j <= 99) ? (float)((j / 10.0) * exp(1.0 - j / 10.0)) : 0.f;
    }
    for (int i = tid; i < FPAD * 32; i += 256) tile[i] = 0.f;
    for (int i = tid; i < (TROWS - FPAD - TT) * 32; i += 256) tile[(FPAD + TT) * 32 + i] = 0.f;
    for (int i = tid; i < TT * 32; i += 256) {
        int t = i >> 5, hl = i & 31;
        tile[(FPAD + t) * 32 + hl] = g_Y1[((size_t)(b * TT + t)) * NHID + h0 + hl];
    }
    __syncthreads();

    int hl = tid & 31, rg = tid >> 5;
    for (int m = 0; m < 6; m++) {
        int t0 = m * 64 + rg * 8;         // 8 outputs per thread
        if (t0 >= TT) break;              // rg uniform per warp -> no divergence
        float s0=0,s1=0,s2=0,s3=0,s4=0,s5=0,s6=0,s7=0;
        int baserow = FPAD + t0 + 7;
        for (int k0 = 1; k0 <= 105; k0 += 8) {
            float e[15];
#pragma unroll
            for (int i = 0; i < 15; i++) e[i] = epsx[k0 + i];
#pragma unroll
            for (int u = 0; u < 8; u++) {
                float x = tile[(baserow - k0 - u) * 32 + hl];
                s0 = fmaf(e[u    ], x, s0);
                s1 = fmaf(e[u + 1], x, s1);
                s2 = fmaf(e[u + 2], x, s2);
                s3 = fmaf(e[u + 3], x, s3);
                s4 = fmaf(e[u + 4], x, s4);
                s5 = fmaf(e[u + 5], x, s5);
                s6 = fmaf(e[u + 6], x, s6);
                s7 = fmaf(e[u + 7], x, s7);
            }
        }
        float acc[8] = {s0,s1,s2,s3,s4,s5,s6,s7};
#pragma unroll
        for (int r = 0; r < 8; r++) {
            int t = t0 + r;
            if (t < TT) usm[t * 32 + hl] = acc[r];
        }
    }
    __syncthreads();

    if (tid < 32) {                        // per-h refractory IIR over t
        float a = 0.f, rb = 0.f;
        size_t obase = ((size_t)b * TT) * NHID + h0 + tid;
        for (int t = 0; t < TT; t++) {
            float u  = usm[t * 32 + tid] + C_REF * rb;
            float s  = (u >= THETA) ? 1.f : 0.f;
            float an = D_REF * a + s;
            rb = D_REF * rb + D_REF * a;
            a  = an;
            g_S1[obase + (size_t)t * NHID] = s;
        }
    }
}

// ---------------- mm2 + FIR2 + spike2, fused per batch --------------------------
#define TAIL_SMEM ((5120 + 32768 + 4490 + 128) * 4)
__global__ void __launch_bounds__(512, 1) k_tail(const float* __restrict__ W2,
                                                 float* __restrict__ out) {
    extern __shared__ float sm[];
    float* sW2  = sm;                        // [10][512]
    float* sS1  = sm + 5120;                 // [64][512] S1 chunk (reused as U2/S2)
    float* sY2  = sm + 5120 + 32768;         // [99+350][10], front zero-padded
    float* seps = sm + 5120 + 32768 + 4490;  // eps[0..99]
    float* sU2  = sS1;                       // [350][10]
    float* sS2  = sS1 + 3500;                // [10][350]
    int tid = threadIdx.x;
    int b   = blockIdx.x;

    for (int i = tid; i < NOUT * NHID; i += 512) sW2[i] = W2[i];
    if (tid < 128) seps[tid] = (tid >= 1 && tid < 100)
                               ? (float)((tid / 10.0) * exp(1.0 - tid / 10.0)) : 0.f;
    for (int i = tid; i < 99 * NOUT; i += 512) sY2[i] = 0.f;

    int wid = tid >> 5, lane = tid & 31;
    for (int tc = 0; tc < TT; tc += 64) {
        int rows = min(64, TT - tc);
        __syncthreads();
        const float4* src = (const float4*)(g_S1 + ((size_t)(b * TT + tc)) * NHID);
        for (int i = tid; i < rows * 128; i += 512) ((float4*)sS1)[i] = src[i];
        __syncthreads();
        for (int task = wid; task < rows * NOUT; task += 16) {
            int t = task / NOUT, o = task - t * NOUT;
            float acc = 0.f;
            const float* sp = sS1 + t * NHID;
            const float* wp = sW2 + o * NHID;
#pragma unroll 4
            for (int h = lane; h < NHID; h += 32) acc = fmaf(sp[h], wp[h], acc);
#pragma unroll
            for (int ofs = 16; ofs; ofs >>= 1) acc += __shfl_down_sync(0xffffffffu, acc, ofs);
            if (lane == 0) sY2[(99 + tc + t) * NOUT + o] = acc;
        }
    }
    __syncthreads();
    for (int i = tid; i < TT * NOUT; i += 512) {         // FIR2
        int t = i / NOUT, o = i - t * NOUT;
        float acc = 0.f;
#pragma unroll 4
        for (int k = 1; k < 100; k++)
            acc = fmaf(seps[k], sY2[(99 + t - k) * NOUT + o], acc);
        sU2[i] = acc;
    }
    __syncthreads();
    if (tid < NOUT) {                                    // spike2 IIR
        float a = 0.f, rb = 0.f;
        for (int t = 0; t < TT; t++) {
            float u  = sU2[t * NOUT + tid] + C_REF * rb;
            float s  = (u >= THETA) ? 1.f : 0.f;
            float an = D_REF * a + s;
            rb = D_REF * rb + D_REF * a;
            a  = an;
            sS2[tid * TT + t] = s;
        }
    }
    __syncthreads();
    for (int i = tid; i < NOUT * TT; i += 512)
        out[(size_t)b * NOUT * TT + i] = sS2[i];
}

extern "C" void kernel_launch(void* const* d_in, const int* in_sizes, int n_in,
                              void* d_out, int out_size) {
    const float* A  = nullptr;   // spikeInput [B][NIN][T]
    const float* W1 = nullptr;   // [NHID][NIN]
    const float* W2 = nullptr;   // [NOUT][NHID]
    for (int i = 0; i < n_in; i++) {
        if      (in_sizes[i] == BB * NIN * TT) A  = (const float*)d_in[i];
        else if (in_sizes[i] == NHID * NIN)    W1 = (const float*)d_in[i];
        else if (in_sizes[i] == NOUT * NHID)   W2 = (const float*)d_in[i];
    }
    float* out = (float*)d_out;

    cudaFuncSetAttribute(k_spmm,       cudaFuncAttributeMaxDynamicSharedMemorySize, SPMM_SMEM);
    cudaFuncSetAttribute(k_fir_spike1, cudaFuncAttributeMaxDynamicSharedMemorySize, FIR_SMEM);
    cudaFuncSetAttribute(k_tail,       cudaFuncAttributeMaxDynamicSharedMemorySize, TAIL_SMEM);

    k_prep   <<<dim3(73, 16), dim3(32, 32)>>>(W1);
    k_pack   <<<dim3(BB, WPT, 11), dim3(32, 32)>>>(A);
    k_extract<<<BB * TT, 128>>>();
    k_spmm   <<<dim3(25, 32), 256, SPMM_SMEM>>>();
    k_fir_spike1<<<512, 256, FIR_SMEM>>>();
    k_tail   <<<BB, 512, TAIL_SMEM>>>(W2, out);
}